// round 4
// baseline (speedup 1.0000x reference)
#include <cuda_runtime.h>
#include <cuda_bf16.h>
#include <math.h>
#include <cstdint>

#define BATCH 4
#define SEQ 4096
#define CDIM 1024
#define HDIM 64
#define MROWS (BATCH * SEQ)   // 16384

// Scratch for projected q/k/v (no cudaMalloc allowed)
__device__ float g_q[(size_t)MROWS * HDIM];
__device__ float g_k[(size_t)MROWS * HDIM];
__device__ float g_v[(size_t)MROWS * HDIM];

// ---------------------------------------------------------------------------
// Packed fp32x2 helpers (Blackwell family-level FFMA2/FMUL2; NOT 'a'-gated)
// ---------------------------------------------------------------------------
__device__ __forceinline__ uint64_t pack2(float lo, float hi) {
    uint64_t r; asm("mov.b64 %0, {%1, %2};" : "=l"(r) : "f"(lo), "f"(hi));
    return r;
}
__device__ __forceinline__ void unpack2(uint64_t v, float& lo, float& hi) {
    asm("mov.b64 {%0, %1}, %2;" : "=f"(lo), "=f"(hi) : "l"(v));
}
__device__ __forceinline__ void ffma2(uint64_t& d, uint64_t a, uint64_t b) {
    asm("fma.rn.f32x2 %0, %1, %2, %3;" : "=l"(d) : "l"(a), "l"(b), "l"(d));
}
__device__ __forceinline__ uint64_t fmul2(uint64_t a, uint64_t b) {
    uint64_t d; asm("mul.rn.f32x2 %0, %1, %2;" : "=l"(d) : "l"(a), "l"(b));
    return d;
}

// ---------------------------------------------------------------------------
// Projection: out = x @ W  (x: [16384, 1024], W: [1024, 64])
// BM=128, BN=64, BK=32; 256 threads; 8x4 outputs/thread as 8x2 packed pairs.
// A staged in smem as duplicated pairs (a,a) so FFMA2 needs no per-use packing.
// ---------------------------------------------------------------------------
__global__ __launch_bounds__(256) void proj_kernel(
    const float* __restrict__ x,
    const float* __restrict__ Wq,
    const float* __restrict__ Wk,
    const float* __restrict__ Wv)
{
    __shared__ float As2[128 * 64];   // row r: (a_k0,a_k0,a_k1,a_k1,...) 32 k dup-pairs
    __shared__ float Bs[32 * 64];     // k-major: Bs[k][n]

    const int which = blockIdx.y;
    const float* __restrict__ W = (which == 0) ? Wq : (which == 1) ? Wk : Wv;
    float* __restrict__ out = (which == 0) ? g_q : (which == 1) ? g_k : g_v;

    const int tid = threadIdx.x;
    const int tc = tid & 15;        // n group: 4 cols (= 2 pairs)
    const int tr = tid >> 4;        // m group: 8 rows
    const int row0 = blockIdx.x * 128;

    uint64_t acc[8][2];
#pragma unroll
    for (int i = 0; i < 8; i++) { acc[i][0] = 0ull; acc[i][1] = 0ull; }

    for (int kc = 0; kc < CDIM; kc += 32) {
        // A: 128x32 -> duplicated pairs (1024 float4 in, 2048 uint4 out)
#pragma unroll
        for (int i = 0; i < 4; i++) {
            int idx = tid + i * 256;        // 0..1023
            int r = idx >> 3;               // 0..127
            int c4 = idx & 7;               // float4 k-group 0..7
            float4 v = *(const float4*)&x[(size_t)(row0 + r) * CDIM + kc + c4 * 4];
            uint32_t ux = __float_as_uint(v.x), uy = __float_as_uint(v.y);
            uint32_t uz = __float_as_uint(v.z), uw = __float_as_uint(v.w);
            uint4 lo = make_uint4(ux, ux, uy, uy);
            uint4 hi = make_uint4(uz, uz, uw, uw);
            *(uint4*)&As2[r * 64 + c4 * 8]     = lo;
            *(uint4*)&As2[r * 64 + c4 * 8 + 4] = hi;
        }
        // B: 32x64 floats = 512 float4
#pragma unroll
        for (int i = 0; i < 2; i++) {
            int idx = tid + i * 256;
            int r = idx >> 4;
            int c4 = idx & 15;
            *(float4*)&Bs[r * 64 + c4 * 4] =
                *(const float4*)&W[(size_t)(kc + r) * HDIM + c4 * 4];
        }
        __syncthreads();

#pragma unroll
        for (int k = 0; k < 32; k += 2) {
            ulonglong2 bA = *(const ulonglong2*)&Bs[(k + 0) * 64 + tc * 4];
            ulonglong2 bB = *(const ulonglong2*)&Bs[(k + 1) * 64 + tc * 4];
#pragma unroll
            for (int i = 0; i < 8; i++) {
                ulonglong2 a2 = *(const ulonglong2*)&As2[(tr * 8 + i) * 64 + 2 * k];
                ffma2(acc[i][0], a2.x, bA.x);
                ffma2(acc[i][1], a2.x, bA.y);
                ffma2(acc[i][0], a2.y, bB.x);
                ffma2(acc[i][1], a2.y, bB.y);
            }
        }
        __syncthreads();
    }

#pragma unroll
    for (int i = 0; i < 8; i++) {
        float4 o;
        unpack2(acc[i][0], o.x, o.y);
        unpack2(acc[i][1], o.z, o.w);
        *(float4*)&out[(size_t)(row0 + tr * 8 + i) * HDIM + tc * 4] = o;
    }
}

// ---------------------------------------------------------------------------
// Flash attention (fp32, causal). 32-query tiles paired (t, 127-t) per CTA.
// 8 warps; warp owns 4 query rows; lane owns key cols {lane, lane+32} for QK,
// and adjacent OUTPUT cols {2*lane, 2*lane+1} for PV (packed f32x2 accum).
// ---------------------------------------------------------------------------
#define KS_STRIDE 68   // 64 keys x 68 floats (16B-aligned rows, conflict-free LDS.128)
#define PS_STRIDE 128  // P duplicated pairs: row -> (p0,p0,p1,p1,...)

__device__ __forceinline__ void attn_tile(
    int b, int t, float* __restrict__ out,
    float* Qs, float* Ks, float* Vs, float* Ps2)
{
    const int tid = threadIdx.x;
    const int warp = tid >> 5;
    const int lane = tid & 31;
    const int wr = warp * 4;
    const int qr0 = t * 32;

    const float* __restrict__ qb = g_q + ((size_t)b * SEQ + qr0) * HDIM;
    const float* __restrict__ kbase = g_k + (size_t)b * SEQ * HDIM;
    const float* __restrict__ vbase = g_v + (size_t)b * SEQ * HDIM;

    __syncthreads();   // previous phase done reading shared tiles
#pragma unroll
    for (int i = 0; i < 2; i++) {
        int idx = tid + i * 256;
        int r = idx >> 4;
        int c4 = idx & 15;
        *(float4*)&Qs[r * HDIM + c4 * 4] =
            *(const float4*)&qb[(size_t)r * HDIM + c4 * 4];
    }

    float m4[4], l4[4];
    uint64_t op[4];    // packed output accum: cols (2*lane, 2*lane+1)
#pragma unroll
    for (int r = 0; r < 4; r++) {
        m4[r] = -INFINITY; l4[r] = 0.0f; op[r] = 0ull;
    }

    const int nkb = t / 2 + 1;
    for (int kb = 0; kb < nkb; kb++) {
        __syncthreads();
        const float* kp = kbase + (size_t)(kb * 64) * HDIM;
        const float* vp = vbase + (size_t)(kb * 64) * HDIM;
#pragma unroll
        for (int i = 0; i < 4; i++) {
            int idx = tid + i * 256;
            int r = idx >> 4;
            int c4 = idx & 15;
            *(float4*)&Ks[r * KS_STRIDE + c4 * 4] =
                *(const float4*)&kp[(size_t)r * HDIM + c4 * 4];
            *(float4*)&Vs[r * HDIM + c4 * 4] =
                *(const float4*)&vp[(size_t)r * HDIM + c4 * 4];
        }
        __syncthreads();

        // S = Q K^T : packed along k (even/odd partial sums), fold at end
        uint64_t s0p[4] = {0ull, 0ull, 0ull, 0ull};
        uint64_t s1p[4] = {0ull, 0ull, 0ull, 0ull};
#pragma unroll
        for (int kk = 0; kk < HDIM; kk += 4) {
            ulonglong2 k0 = *(const ulonglong2*)&Ks[lane * KS_STRIDE + kk];
            ulonglong2 k1 = *(const ulonglong2*)&Ks[(lane + 32) * KS_STRIDE + kk];
#pragma unroll
            for (int r = 0; r < 4; r++) {
                ulonglong2 q = *(const ulonglong2*)&Qs[(wr + r) * HDIM + kk];
                ffma2(s0p[r], q.x, k0.x);
                ffma2(s0p[r], q.y, k0.y);
                ffma2(s1p[r], q.x, k1.x);
                ffma2(s1p[r], q.y, k1.y);
            }
        }

        // online softmax (scalar), P written as duplicated pairs
        const bool maskb = (kb == nkb - 1);
#pragma unroll
        for (int r = 0; r < 4; r++) {
            const int rq = qr0 + wr + r;
            float a0, a1, b0, b1;
            unpack2(s0p[r], a0, a1);
            unpack2(s1p[r], b0, b1);
            float v0 = (a0 + a1) * 0.125f;   // 1/sqrt(64)
            float v1 = (b0 + b1) * 0.125f;
            if (maskb) {
                int kg = kb * 64 + lane;
                if (kg > rq)      v0 = -1e30f;
                if (kg + 32 > rq) v1 = -1e30f;
            }
            float mx = fmaxf(v0, v1);
#pragma unroll
            for (int off = 16; off > 0; off >>= 1)
                mx = fmaxf(mx, __shfl_xor_sync(0xffffffffu, mx, off));
            float mnew = fmaxf(m4[r], mx);
            float p0 = __expf(v0 - mnew);
            float p1 = __expf(v1 - mnew);
            float alpha = __expf(m4[r] - mnew);
            float ps = p0 + p1;
#pragma unroll
            for (int off = 16; off > 0; off >>= 1)
                ps += __shfl_xor_sync(0xffffffffu, ps, off);
            l4[r] = l4[r] * alpha + ps;
            m4[r] = mnew;
            op[r] = fmul2(op[r], pack2(alpha, alpha));
            *(uint64_t*)&Ps2[(wr + r) * PS_STRIDE + 2 * lane]        = pack2(p0, p0);
            *(uint64_t*)&Ps2[(wr + r) * PS_STRIDE + 2 * (lane + 32)] = pack2(p1, p1);
        }
        __syncwarp();   // Ps2 written/read within this warp only

        // O += P @ V : pp broadcast LDS.128 (2 dup pairs), v float2 per s
#pragma unroll
        for (int s = 0; s < 64; s += 4) {
            uint64_t vv0 = *(const uint64_t*)&Vs[(s + 0) * HDIM + 2 * lane];
            uint64_t vv1 = *(const uint64_t*)&Vs[(s + 1) * HDIM + 2 * lane];
            uint64_t vv2 = *(const uint64_t*)&Vs[(s + 2) * HDIM + 2 * lane];
            uint64_t vv3 = *(const uint64_t*)&Vs[(s + 3) * HDIM + 2 * lane];
#pragma unroll
            for (int r = 0; r < 4; r++) {
                ulonglong2 ppA = *(const ulonglong2*)&Ps2[(wr + r) * PS_STRIDE + 2 * s];
                ulonglong2 ppB = *(const ulonglong2*)&Ps2[(wr + r) * PS_STRIDE + 2 * s + 4];
                ffma2(op[r], ppA.x, vv0);
                ffma2(op[r], ppA.y, vv1);
                ffma2(op[r], ppB.x, vv2);
                ffma2(op[r], ppB.y, vv3);
            }
        }
    }

    float* ob = out + ((size_t)b * SEQ + qr0) * HDIM;
#pragma unroll
    for (int r = 0; r < 4; r++) {
        float inv = 1.0f / l4[r];
        float olo, ohi;
        unpack2(op[r], olo, ohi);
        float2 o2 = make_float2(olo * inv, ohi * inv);
        *(float2*)&ob[(size_t)(wr + r) * HDIM + 2 * lane] = o2;
    }
}

__global__ __launch_bounds__(256) void attn_kernel(float* __restrict__ out)
{
    extern __shared__ float sm[];
    float* Qs  = sm;                       // 32 x 64
    float* Ks  = Qs + 32 * HDIM;           // 64 x 68
    float* Vs  = Ks + 64 * KS_STRIDE;      // 64 x 64
    float* Ps2 = Vs + 64 * HDIM;           // 32 x 128 (dup pairs)

    const int b = blockIdx.y;
    const int pair = blockIdx.x;           // 0..63

    attn_tile(b, pair, out, Qs, Ks, Vs, Ps2);
    attn_tile(b, 127 - pair, out, Qs, Ks, Vs, Ps2);
}

// ---------------------------------------------------------------------------
extern "C" void kernel_launch(void* const* d_in, const int* in_sizes, int n_in,
                              void* d_out, int out_size)
{
    const float* x  = (const float*)d_in[0];
    const float* Wk = (const float*)d_in[1];
    const float* Wq = (const float*)d_in[2];
    const float* Wv = (const float*)d_in[3];
    float* out = (float*)d_out;

    dim3 pgrid(MROWS / 128, 3);
    proj_kernel<<<pgrid, 256>>>(x, Wq, Wk, Wv);

    const int smem = (32 * HDIM + 64 * KS_STRIDE + 64 * HDIM + 32 * PS_STRIDE)
                     * (int)sizeof(float);
    cudaFuncSetAttribute(attn_kernel, cudaFuncAttributeMaxDynamicSharedMemorySize, smem);
    dim3 agrid(64, BATCH);
    attn_kernel<<<agrid, 256, smem>>>(out);
}

// round 5
// speedup vs baseline: 2.8858x; 2.8858x over previous
#include <cuda_runtime.h>
#include <cuda_bf16.h>
#include <math.h>
#include <cstdint>

#define BATCH 4
#define SEQ 4096
#define CDIM 1024
#define HDIM 64
#define MROWS (BATCH * SEQ)   // 16384

// Scratch (no cudaMalloc allowed)
__device__ float g_q[(size_t)MROWS * HDIM];
__device__ float g_k[(size_t)MROWS * HDIM];
__device__ float g_v[(size_t)MROWS * HDIM];
__device__ float g_osc[2][(size_t)MROWS * HDIM];   // split partial O
__device__ float g_ml[2][(size_t)MROWS * 2];       // split (m, l)

// ---------------------------------------------------------------------------
// tf32 mma.sync helpers (sm_80-era PTX; family-safe, NOT 'a'-gated)
// ---------------------------------------------------------------------------
__device__ __forceinline__ uint32_t to_tf32(float f) {
    uint32_t r;
    asm("cvt.rna.tf32.f32 %0, %1;" : "=r"(r) : "f"(f));
    return r;
}
__device__ __forceinline__ void mma_tf32(float* c, const uint32_t* a, const uint32_t* b) {
    asm volatile(
        "mma.sync.aligned.m16n8k8.row.col.f32.tf32.tf32.f32 "
        "{%0,%1,%2,%3}, {%4,%5,%6,%7}, {%8,%9}, {%0,%1,%2,%3};\n"
        : "+f"(c[0]), "+f"(c[1]), "+f"(c[2]), "+f"(c[3])
        : "r"(a[0]), "r"(a[1]), "r"(a[2]), "r"(a[3]), "r"(b[0]), "r"(b[1]));
}
__device__ __forceinline__ float qmax(float v) {
    v = fmaxf(v, __shfl_xor_sync(0xffffffffu, v, 1));
    v = fmaxf(v, __shfl_xor_sync(0xffffffffu, v, 2));
    return v;
}
__device__ __forceinline__ float qsum(float v) {
    v += __shfl_xor_sync(0xffffffffu, v, 1);
    v += __shfl_xor_sync(0xffffffffu, v, 2);
    return v;
}
__device__ __forceinline__ uint4 cvt4(float4 v) {
    uint4 t;
    t.x = to_tf32(v.x); t.y = to_tf32(v.y); t.z = to_tf32(v.z); t.w = to_tf32(v.w);
    return t;
}

// ---------------------------------------------------------------------------
// Projection via tf32 mma: out = x @ W  (x:[16384,1024], W:[1024,64])
// BM=128 (8 warps x m16), N=64 (8 n-tiles), BK=64.
// Strides: As 68 (banks 4*grp+tig), Bs 72 (banks 8*tig+grp) -> conflict-free.
// ---------------------------------------------------------------------------
#define PAS 68
#define PBS 72
#define PROJ_SMEM ((128 * PAS + 64 * PBS) * 4)

__global__ __launch_bounds__(256) void proj_tc(
    const float* __restrict__ x,
    const float* __restrict__ Wq,
    const float* __restrict__ Wk,
    const float* __restrict__ Wv)
{
    extern __shared__ float sm[];
    float* As = sm;                // [128][68] tf32 bits
    float* Bs = sm + 128 * PAS;    // [64][72]

    const int which = blockIdx.y;
    const float* __restrict__ W = (which == 0) ? Wq : (which == 1) ? Wk : Wv;
    float* __restrict__ out = (which == 0) ? g_q : (which == 1) ? g_k : g_v;

    const int tid = threadIdx.x;
    const int warp = tid >> 5;
    const int lane = tid & 31;
    const int grp = lane >> 2;
    const int tig = lane & 3;
    const int row0 = blockIdx.x * 128;

    float acc[8][4];
#pragma unroll
    for (int j = 0; j < 8; j++)
#pragma unroll
        for (int e = 0; e < 4; e++) acc[j][e] = 0.0f;

    const uint32_t* Au = (const uint32_t*)As;
    const uint32_t* Bu = (const uint32_t*)Bs;

    for (int kc = 0; kc < CDIM; kc += 64) {
        __syncthreads();
        // A: 128x64 -> 2048 float4, 8/thread
#pragma unroll
        for (int i = 0; i < 8; i++) {
            int idx = tid + i * 256;
            int r = idx >> 4;
            int c4 = idx & 15;
            float4 v = *(const float4*)&x[(size_t)(row0 + r) * CDIM + kc + c4 * 4];
            *(uint4*)&As[r * PAS + c4 * 4] = cvt4(v);
        }
        // B: 64x64 -> 1024 float4, 4/thread
#pragma unroll
        for (int i = 0; i < 4; i++) {
            int idx = tid + i * 256;
            int r = idx >> 4;
            int c4 = idx & 15;
            float4 v = *(const float4*)&W[(size_t)(kc + r) * HDIM + c4 * 4];
            *(uint4*)&Bs[r * PBS + c4 * 4] = cvt4(v);
        }
        __syncthreads();

#pragma unroll
        for (int ks = 0; ks < 8; ks++) {
            uint32_t a[4];
            a[0] = Au[(16 * warp + grp) * PAS + 8 * ks + tig];
            a[1] = Au[(16 * warp + grp + 8) * PAS + 8 * ks + tig];
            a[2] = Au[(16 * warp + grp) * PAS + 8 * ks + tig + 4];
            a[3] = Au[(16 * warp + grp + 8) * PAS + 8 * ks + tig + 4];
#pragma unroll
            for (int j = 0; j < 8; j++) {
                uint32_t b[2];
                b[0] = Bu[(8 * ks + tig) * PBS + 8 * j + grp];
                b[1] = Bu[(8 * ks + tig + 4) * PBS + 8 * j + grp];
                mma_tf32(acc[j], a, b);
            }
        }
    }

    const int r0 = row0 + 16 * warp + grp;
#pragma unroll
    for (int j = 0; j < 8; j++) {
        *(float2*)&out[(size_t)r0 * HDIM + 8 * j + 2 * tig] =
            make_float2(acc[j][0], acc[j][1]);
        *(float2*)&out[(size_t)(r0 + 8) * HDIM + 8 * j + 2 * tig] =
            make_float2(acc[j][2], acc[j][3]);
    }
}

// ---------------------------------------------------------------------------
// Attention via tf32 mma. 64-row Q tiles, 4 warps x 16 rows, warp owns full
// key range -> warp-local online softmax. Split-K by kb parity + tile pairing
// (t, 63-t) -> 256 equal CTAs. Partials (O, m, l) merged by merge_kernel.
// ---------------------------------------------------------------------------
#define AQS 68   // Qs/Ks stride: banks 4*grp+tig
#define AVS 72   // Vs/Ps stride: banks 8*tig+grp (V) / 8*grp+tig (P)
#define ATTN_SMEM ((64 * AQS + 64 * AQS + 64 * AVS + 64 * AVS) * 4)

__device__ __forceinline__ void attn_tile_tc(
    int b, int t, int split,
    float* Qs, float* Ks, float* Vs, float* Ps)
{
    const int tid = threadIdx.x;
    const int mg = tid >> 5;          // warp 0..3 -> rows 16*mg..16*mg+15
    const int lane = tid & 31;
    const int grp = lane >> 2;
    const int tig = lane & 3;

    const uint32_t* Qu = (const uint32_t*)Qs;
    const uint32_t* Ku = (const uint32_t*)Ks;
    const uint32_t* Vu = (const uint32_t*)Vs;
    const uint32_t* Pu = (const uint32_t*)Ps;

    __syncthreads();   // previous tile done with smem
    // Q (pre-scaled by 1/sqrt(64)): 64x64 -> 1024 float4, 8/thread
    const float* qb = g_q + ((size_t)b * SEQ + 64 * t) * HDIM;
#pragma unroll
    for (int i = 0; i < 8; i++) {
        int idx = tid + i * 128;
        int r = idx >> 4;
        int c4 = idx & 15;
        float4 v = *(const float4*)&qb[(size_t)r * HDIM + c4 * 4];
        v.x *= 0.125f; v.y *= 0.125f; v.z *= 0.125f; v.w *= 0.125f;
        *(uint4*)&Qs[r * AQS + c4 * 4] = cvt4(v);
    }

    float O[8][4];
#pragma unroll
    for (int j = 0; j < 8; j++)
#pragma unroll
        for (int e = 0; e < 4; e++) O[j][e] = 0.0f;
    float mrow[2] = {-1e30f, -1e30f};
    float lrow[2] = {0.0f, 0.0f};

    const float* kbase = g_k + (size_t)b * SEQ * HDIM;
    const float* vbase = g_v + (size_t)b * SEQ * HDIM;

    for (int kb = split; kb <= t; kb += 2) {
        __syncthreads();
        const float* kp = kbase + (size_t)(64 * kb) * HDIM;
        const float* vp = vbase + (size_t)(64 * kb) * HDIM;
#pragma unroll
        for (int i = 0; i < 8; i++) {
            int idx = tid + i * 128;
            int r = idx >> 4;
            int c4 = idx & 15;
            float4 kv = *(const float4*)&kp[(size_t)r * HDIM + c4 * 4];
            *(uint4*)&Ks[r * AQS + c4 * 4] = cvt4(kv);
            float4 vv = *(const float4*)&vp[(size_t)r * HDIM + c4 * 4];
            *(uint4*)&Vs[r * AVS + c4 * 4] = cvt4(vv);
        }
        __syncthreads();

        const bool diag = (kb == t);
        const int jmax = diag ? (2 * mg + 1) : 7;   // key n-tiles this warp needs

        // --- S = Q K^T ---
        float S[8][4];
#pragma unroll
        for (int j = 0; j < 8; j++)
#pragma unroll
            for (int e = 0; e < 4; e++) S[j][e] = 0.0f;
#pragma unroll
        for (int ks = 0; ks < 8; ks++) {
            uint32_t a[4];
            a[0] = Qu[(16 * mg + grp) * AQS + 8 * ks + tig];
            a[1] = Qu[(16 * mg + grp + 8) * AQS + 8 * ks + tig];
            a[2] = Qu[(16 * mg + grp) * AQS + 8 * ks + tig + 4];
            a[3] = Qu[(16 * mg + grp + 8) * AQS + 8 * ks + tig + 4];
#pragma unroll
            for (int j = 0; j < 8; j++) {
                if (j <= jmax) {
                    uint32_t bf[2];
                    bf[0] = Ku[(8 * j + grp) * AQS + 8 * ks + tig];
                    bf[1] = Ku[(8 * j + grp) * AQS + 8 * ks + tig + 4];
                    mma_tf32(S[j], a, bf);
                }
            }
        }

        // --- mask diagonal block ---
        if (diag) {
#pragma unroll
            for (int j = 0; j < 8; j++) {
                if (j <= jmax) {
#pragma unroll
                    for (int e = 0; e < 2; e++) {
                        int key = 8 * j + 2 * tig + e;
                        if (key > 16 * mg + grp)     S[j][e]     = -1e30f;
                        if (key > 16 * mg + grp + 8) S[j][2 + e] = -1e30f;
                    }
                }
            }
        }

        // --- online softmax (rows: A = 16mg+grp, B = +8) ---
        float mA = -1e30f, mB = -1e30f;
#pragma unroll
        for (int j = 0; j < 8; j++) {
            if (j <= jmax) {
                mA = fmaxf(mA, fmaxf(S[j][0], S[j][1]));
                mB = fmaxf(mB, fmaxf(S[j][2], S[j][3]));
            }
        }
        mA = qmax(mA); mB = qmax(mB);
        float mnA = fmaxf(mrow[0], mA), mnB = fmaxf(mrow[1], mB);
        float alA = __expf(mrow[0] - mnA), alB = __expf(mrow[1] - mnB);
        float sA = 0.0f, sB = 0.0f;
#pragma unroll
        for (int j = 0; j < 8; j++) {
            if (j <= jmax) {
                float p00 = __expf(S[j][0] - mnA);
                float p01 = __expf(S[j][1] - mnA);
                float p10 = __expf(S[j][2] - mnB);
                float p11 = __expf(S[j][3] - mnB);
                sA += p00 + p01; sB += p10 + p11;
                *(uint2*)&Ps[(16 * mg + grp) * AVS + 8 * j + 2 * tig] =
                    make_uint2(to_tf32(p00), to_tf32(p01));
                *(uint2*)&Ps[(16 * mg + grp + 8) * AVS + 8 * j + 2 * tig] =
                    make_uint2(to_tf32(p10), to_tf32(p11));
            }
        }
        sA = qsum(sA); sB = qsum(sB);
        lrow[0] = lrow[0] * alA + sA; mrow[0] = mnA;
        lrow[1] = lrow[1] * alB + sB; mrow[1] = mnB;
#pragma unroll
        for (int j = 0; j < 8; j++) {
            O[j][0] *= alA; O[j][1] *= alA;
            O[j][2] *= alB; O[j][3] *= alB;
        }
        __syncwarp();   // Ps produced/consumed within this warp only

        // --- O += P @ V ---  (j = hdim n-tiles, always all 8; ks = key steps)
#pragma unroll
        for (int ks = 0; ks < 8; ks++) {
            if (ks <= jmax) {
                uint32_t pa[4];
                pa[0] = Pu[(16 * mg + grp) * AVS + 8 * ks + tig];
                pa[1] = Pu[(16 * mg + grp + 8) * AVS + 8 * ks + tig];
                pa[2] = Pu[(16 * mg + grp) * AVS + 8 * ks + tig + 4];
                pa[3] = Pu[(16 * mg + grp + 8) * AVS + 8 * ks + tig + 4];
#pragma unroll
                for (int j = 0; j < 8; j++) {
                    uint32_t vb[2];
                    vb[0] = Vu[(8 * ks + tig) * AVS + 8 * j + grp];
                    vb[1] = Vu[(8 * ks + tig + 4) * AVS + 8 * j + grp];
                    mma_tf32(O[j], pa, vb);
                }
            }
        }
    }

    // write split partials
    const size_t row = (size_t)b * SEQ + 64 * t + 16 * mg + grp;
#pragma unroll
    for (int j = 0; j < 8; j++) {
        *(float2*)&g_osc[split][row * HDIM + 8 * j + 2 * tig] =
            make_float2(O[j][0], O[j][1]);
        *(float2*)&g_osc[split][(row + 8) * HDIM + 8 * j + 2 * tig] =
            make_float2(O[j][2], O[j][3]);
    }
    if (tig == 0) {
        g_ml[split][row * 2]           = mrow[0];
        g_ml[split][row * 2 + 1]       = lrow[0];
        g_ml[split][(row + 8) * 2]     = mrow[1];
        g_ml[split][(row + 8) * 2 + 1] = lrow[1];
    }
}

__global__ __launch_bounds__(128) void attn_tc(void)
{
    extern __shared__ float sm[];
    float* Qs = sm;                 // 64 x 68
    float* Ks = Qs + 64 * AQS;      // 64 x 68
    float* Vs = Ks + 64 * AQS;      // 64 x 72
    float* Ps = Vs + 64 * AVS;      // 64 x 72

    const int pair = blockIdx.x;    // 0..31
    const int split = blockIdx.y;   // 0..1
    const int b = blockIdx.z;

    attn_tile_tc(b, pair, split, Qs, Ks, Vs, Ps);
    attn_tile_tc(b, 63 - pair, split, Qs, Ks, Vs, Ps);
}

// ---------------------------------------------------------------------------
// Merge split partials: z = (w0*O0 + w1*O1) / (w0*l0 + w1*l1)
// ---------------------------------------------------------------------------
__global__ __launch_bounds__(128) void merge_kernel(float* __restrict__ out)
{
    const size_t row = (size_t)blockIdx.x * 128 + threadIdx.x;   // 0..16383
    float m0 = g_ml[0][row * 2], l0 = g_ml[0][row * 2 + 1];
    float m1 = g_ml[1][row * 2], l1 = g_ml[1][row * 2 + 1];
    float mm = fmaxf(m0, m1);
    float w0 = __expf(m0 - mm), w1 = __expf(m1 - mm);
    float inv = 1.0f / (w0 * l0 + w1 * l1);
    w0 *= inv; w1 *= inv;
#pragma unroll
    for (int c4 = 0; c4 < 16; c4++) {
        float4 a = *(const float4*)&g_osc[0][row * HDIM + c4 * 4];
        float4 c = *(const float4*)&g_osc[1][row * HDIM + c4 * 4];
        float4 o = make_float4(w0 * a.x + w1 * c.x, w0 * a.y + w1 * c.y,
                               w0 * a.z + w1 * c.z, w0 * a.w + w1 * c.w);
        *(float4*)&out[row * HDIM + c4 * 4] = o;
    }
}

// ---------------------------------------------------------------------------
extern "C" void kernel_launch(void* const* d_in, const int* in_sizes, int n_in,
                              void* d_out, int out_size)
{
    const float* x  = (const float*)d_in[0];
    const float* Wk = (const float*)d_in[1];
    const float* Wq = (const float*)d_in[2];
    const float* Wv = (const float*)d_in[3];
    float* out = (float*)d_out;

    cudaFuncSetAttribute(proj_tc, cudaFuncAttributeMaxDynamicSharedMemorySize, PROJ_SMEM);
    cudaFuncSetAttribute(attn_tc, cudaFuncAttributeMaxDynamicSharedMemorySize, ATTN_SMEM);

    dim3 pgrid(MROWS / 128, 3);
    proj_tc<<<pgrid, 256, PROJ_SMEM>>>(x, Wq, Wk, Wv);

    dim3 agrid(32, 2, BATCH);
    attn_tc<<<agrid, 128, ATTN_SMEM>>>();

    merge_kernel<<<MROWS / 128, 128>>>(out);
}

// round 9
// speedup vs baseline: 2.9140x; 1.0098x over previous
#include <cuda_runtime.h>
#include <cuda_bf16.h>
#include <math.h>
#include <cstdint>

#define BATCH 4
#define SEQ 4096
#define CDIM 1024
#define HDIM 64
#define MROWS (BATCH * SEQ)   // 16384

// Scratch (no cudaMalloc allowed). g_q/g_k/g_v hold tf32-rounded floats;
// g_q additionally pre-scaled by 1/sqrt(64).
__device__ float g_q[(size_t)MROWS * HDIM];
__device__ float g_k[(size_t)MROWS * HDIM];
__device__ float g_v[(size_t)MROWS * HDIM];
__device__ float g_osc[2][(size_t)MROWS * HDIM];   // split partial O
__device__ float g_ml[2][(size_t)MROWS * 2];       // split (m, l)

// ---------------------------------------------------------------------------
// tf32 mma.sync helpers (sm_80-era PTX; family-safe)
// ---------------------------------------------------------------------------
__device__ __forceinline__ uint32_t to_tf32(float f) {
    uint32_t r;
    asm("cvt.rna.tf32.f32 %0, %1;" : "=r"(r) : "f"(f));
    return r;
}
__device__ __forceinline__ void mma_tf32(float* c, const uint32_t* a, const uint32_t* b) {
    asm volatile(
        "mma.sync.aligned.m16n8k8.row.col.f32.tf32.tf32.f32 "
        "{%0,%1,%2,%3}, {%4,%5,%6,%7}, {%8,%9}, {%0,%1,%2,%3};\n"
        : "+f"(c[0]), "+f"(c[1]), "+f"(c[2]), "+f"(c[3])
        : "r"(a[0]), "r"(a[1]), "r"(a[2]), "r"(a[3]), "r"(b[0]), "r"(b[1]));
}
__device__ __forceinline__ float qmax(float v) {
    v = fmaxf(v, __shfl_xor_sync(0xffffffffu, v, 1));
    v = fmaxf(v, __shfl_xor_sync(0xffffffffu, v, 2));
    return v;
}
__device__ __forceinline__ float qsum(float v) {
    v += __shfl_xor_sync(0xffffffffu, v, 1);
    v += __shfl_xor_sync(0xffffffffu, v, 2);
    return v;
}
__device__ __forceinline__ uint4 cvt4(float4 v) {
    uint4 t;
    t.x = to_tf32(v.x); t.y = to_tf32(v.y); t.z = to_tf32(v.z); t.w = to_tf32(v.w);
    return t;
}

// ---------------------------------------------------------------------------
// Projection via tf32 mma, double-buffered: out = tf32(scale * (x @ W))
// BM=128 (8 warps x m16), N=64 (8 n-tiles), BK=32, 32 pipelined k-iters.
// ---------------------------------------------------------------------------
#define PAS 36   // A stride: banks (4r+c), frag lanes 4*grp+tig -> conflict-free
#define PBS 72   // B stride: banks (8r+c), frag lanes 8*tig+grp -> conflict-free
#define PBUF (128 * PAS + 32 * PBS)
#define PROJ_SMEM (2 * PBUF * 4)

__global__ __launch_bounds__(256) void proj_tc(
    const float* __restrict__ x,
    const float* __restrict__ Wq,
    const float* __restrict__ Wk,
    const float* __restrict__ Wv)
{
    extern __shared__ float sm[];

    const int which = blockIdx.y;
    const float* __restrict__ W = (which == 0) ? Wq : (which == 1) ? Wk : Wv;
    float* __restrict__ out = (which == 0) ? g_q : (which == 1) ? g_k : g_v;
    const float scale = (which == 0) ? 0.125f : 1.0f;

    const int tid = threadIdx.x;
    const int warp = tid >> 5;
    const int lane = tid & 31;
    const int grp = lane >> 2;
    const int tig = lane & 3;
    const int row0 = blockIdx.x * 128;

    // per-thread load coords
    // A: 128 rows x 8 float4; 2 threads/row, 4 contiguous float4 each (FULL row)
    const int ar = tid >> 1;                  // A row 0..127
    const int ac4 = (tid & 1) * 4;            // A float4 col base {0,4}
    // B: 32 rows x 16 float4; 8 threads/row, 2 float4 each (cols bc4, bc4+8)
    const int br = tid >> 3;                  // B row 0..31
    const int bc4 = tid & 7;                  // B float4 col 0..7 (+8)

    float acc[8][4];
#pragma unroll
    for (int j = 0; j < 8; j++)
#pragma unroll
        for (int e = 0; e < 4; e++) acc[j][e] = 0.0f;

    float4 aR[4], bR[2];
    // prologue: load kc-chunk 0
#pragma unroll
    for (int i = 0; i < 4; i++)
        aR[i] = *(const float4*)&x[(size_t)(row0 + ar) * CDIM + (ac4 + i) * 4];
#pragma unroll
    for (int i = 0; i < 2; i++)
        bR[i] = *(const float4*)&W[(size_t)br * HDIM + (bc4 + i * 8) * 4];
    {
        float* As = sm;
        float* Bs = sm + 128 * PAS;
#pragma unroll
        for (int i = 0; i < 4; i++)
            *(uint4*)&As[ar * PAS + (ac4 + i) * 4] = cvt4(aR[i]);
#pragma unroll
        for (int i = 0; i < 2; i++)
            *(uint4*)&Bs[br * PBS + (bc4 + i * 8) * 4] = cvt4(bR[i]);
    }
    __syncthreads();

    for (int it = 0; it < 32; it++) {
        const int cur = it & 1;
        const bool hn = (it < 31);
        const uint32_t* Au = (const uint32_t*)(sm + cur * PBUF);
        const uint32_t* Bu = Au + 128 * PAS;

        if (hn) {
            const int kc = (it + 1) * 32;
#pragma unroll
            for (int i = 0; i < 4; i++)
                aR[i] = *(const float4*)&x[(size_t)(row0 + ar) * CDIM + kc + (ac4 + i) * 4];
#pragma unroll
            for (int i = 0; i < 2; i++)
                bR[i] = *(const float4*)&W[(size_t)(kc + br) * HDIM + (bc4 + i * 8) * 4];
        }

#pragma unroll
        for (int ks = 0; ks < 4; ks++) {
            uint32_t a[4];
            a[0] = Au[(16 * warp + grp) * PAS + 8 * ks + tig];
            a[1] = Au[(16 * warp + grp + 8) * PAS + 8 * ks + tig];
            a[2] = Au[(16 * warp + grp) * PAS + 8 * ks + tig + 4];
            a[3] = Au[(16 * warp + grp + 8) * PAS + 8 * ks + tig + 4];
#pragma unroll
            for (int j = 0; j < 8; j++) {
                uint32_t b[2];
                b[0] = Bu[(8 * ks + tig) * PBS + 8 * j + grp];
                b[1] = Bu[(8 * ks + tig + 4) * PBS + 8 * j + grp];
                mma_tf32(acc[j], a, b);
            }
        }

        if (hn) {
            float* As = sm + (cur ^ 1) * PBUF;
            float* Bs = As + 128 * PAS;
#pragma unroll
            for (int i = 0; i < 4; i++)
                *(uint4*)&As[ar * PAS + (ac4 + i) * 4] = cvt4(aR[i]);
#pragma unroll
            for (int i = 0; i < 2; i++)
                *(uint4*)&Bs[br * PBS + (bc4 + i * 8) * 4] = cvt4(bR[i]);
        }
        __syncthreads();
    }

    // epilogue: tf32-round (and pre-scale for Q) so attn loads raw
    const int r0 = row0 + 16 * warp + grp;
#pragma unroll
    for (int j = 0; j < 8; j++) {
        float2 lo = make_float2(
            __uint_as_float(to_tf32(scale * acc[j][0])),
            __uint_as_float(to_tf32(scale * acc[j][1])));
        float2 hi = make_float2(
            __uint_as_float(to_tf32(scale * acc[j][2])),
            __uint_as_float(to_tf32(scale * acc[j][3])));
        *(float2*)&out[(size_t)r0 * HDIM + 8 * j + 2 * tig] = lo;
        *(float2*)&out[(size_t)(r0 + 8) * HDIM + 8 * j + 2 * tig] = hi;
    }
}

// ---------------------------------------------------------------------------
// Attention via tf32 mma, K/V double-buffered prefetch pipeline.
// 64-row Q tiles, 4 warps x 16 rows; warp-local online softmax.
// Split-K parity + tile pairing (t, 63-t) -> 256 equal CTAs.
// ---------------------------------------------------------------------------
#define AQS 68   // Q/K stride
#define AVS 72   // V stride
#define APS 68   // P stride
#define KBUF (64 * AQS)
#define VBUF (64 * AVS)
#define ATTN_SMEM ((64 * AQS + 2 * KBUF + 2 * VBUF + 64 * APS) * 4)

__device__ __forceinline__ void attn_tile_tc(
    int b, int t, int split,
    float* Qs, float* Ks, float* Vs, float* Ps)
{
    const int tid = threadIdx.x;
    const int mg = tid >> 5;
    const int lane = tid & 31;
    const int grp = lane >> 2;
    const int tig = lane & 3;
    // load coords (128 threads): 8 rows of float4 each
    const int lr = tid >> 4;      // base row 0..7 (step 8)
    const int lc4 = tid & 15;     // float4 col 0..15

    const float* kbase = g_k + (size_t)b * SEQ * HDIM;
    const float* vbase = g_v + (size_t)b * SEQ * HDIM;

    __syncthreads();
    // Q tile (raw copy; pre-scaled tf32 from proj)
    const float* qb = g_q + ((size_t)b * SEQ + 64 * t) * HDIM;
#pragma unroll
    for (int i = 0; i < 8; i++)
        *(float4*)&Qs[(lr + 8 * i) * AQS + lc4 * 4] =
            *(const float4*)&qb[(size_t)(lr + 8 * i) * HDIM + lc4 * 4];

    // prologue: first kb into buffer 0
    if (split <= t) {
        const float* kp = kbase + (size_t)(64 * split) * HDIM;
        const float* vp = vbase + (size_t)(64 * split) * HDIM;
#pragma unroll
        for (int i = 0; i < 8; i++) {
            *(float4*)&Ks[(lr + 8 * i) * AQS + lc4 * 4] =
                *(const float4*)&kp[(size_t)(lr + 8 * i) * HDIM + lc4 * 4];
            *(float4*)&Vs[(lr + 8 * i) * AVS + lc4 * 4] =
                *(const float4*)&vp[(size_t)(lr + 8 * i) * HDIM + lc4 * 4];
        }
    }
    __syncthreads();

    float O[8][4];
#pragma unroll
    for (int j = 0; j < 8; j++)
#pragma unroll
        for (int e = 0; e < 4; e++) O[j][e] = 0.0f;
    float mrow[2] = {-1e30f, -1e30f};
    float lrow[2] = {0.0f, 0.0f};

    const uint32_t* Qu = (const uint32_t*)Qs;
    const uint32_t* Pu = (const uint32_t*)Ps;

    int idx = 0;
    for (int kb = split; kb <= t; kb += 2, idx++) {
        const int cur = idx & 1;
        const bool hn = (kb + 2 <= t);
        const uint32_t* Ku = (const uint32_t*)(Ks + cur * KBUF);
        const uint32_t* Vu = (const uint32_t*)(Vs + cur * VBUF);

        // ---- prefetch next K into regs (overlaps S-mma) ----
        float4 kreg[8];
        if (hn) {
            const float* kp = kbase + (size_t)(64 * (kb + 2)) * HDIM;
#pragma unroll
            for (int i = 0; i < 8; i++)
                kreg[i] = *(const float4*)&kp[(size_t)(lr + 8 * i) * HDIM + lc4 * 4];
        }

        const bool diag = (kb == t);
        const int jmax = diag ? (2 * mg + 1) : 7;

        // ---- S = Q K^T ----
        float S[8][4];
#pragma unroll
        for (int j = 0; j < 8; j++)
#pragma unroll
            for (int e = 0; e < 4; e++) S[j][e] = 0.0f;
#pragma unroll
        for (int ks = 0; ks < 8; ks++) {
            uint32_t a[4];
            a[0] = Qu[(16 * mg + grp) * AQS + 8 * ks + tig];
            a[1] = Qu[(16 * mg + grp + 8) * AQS + 8 * ks + tig];
            a[2] = Qu[(16 * mg + grp) * AQS + 8 * ks + tig + 4];
            a[3] = Qu[(16 * mg + grp + 8) * AQS + 8 * ks + tig + 4];
#pragma unroll
            for (int j = 0; j < 8; j++) {
                if (j <= jmax) {
                    uint32_t bf[2];
                    bf[0] = Ku[(8 * j + grp) * AQS + 8 * ks + tig];
                    bf[1] = Ku[(8 * j + grp) * AQS + 8 * ks + tig + 4];
                    mma_tf32(S[j], a, bf);
                }
            }
        }

        // ---- stage next K into other buffer (kregs die here) ----
        if (hn) {
            float* Kn = Ks + (cur ^ 1) * KBUF;
#pragma unroll
            for (int i = 0; i < 8; i++)
                *(float4*)&Kn[(lr + 8 * i) * AQS + lc4 * 4] = kreg[i];
        }

        // ---- prefetch next V into regs (overlaps softmax + PV) ----
        float4 vreg[8];
        if (hn) {
            const float* vp = vbase + (size_t)(64 * (kb + 2)) * HDIM;
#pragma unroll
            for (int i = 0; i < 8; i++)
                vreg[i] = *(const float4*)&vp[(size_t)(lr + 8 * i) * HDIM + lc4 * 4];
        }

        // ---- mask diagonal ----
        if (diag) {
#pragma unroll
            for (int j = 0; j < 8; j++) {
                if (j <= jmax) {
#pragma unroll
                    for (int e = 0; e < 2; e++) {
                        int key = 8 * j + 2 * tig + e;
                        if (key > 16 * mg + grp)     S[j][e]     = -1e30f;
                        if (key > 16 * mg + grp + 8) S[j][2 + e] = -1e30f;
                    }
                }
            }
        }

        // ---- online softmax ----
        float mA = -1e30f, mB = -1e30f;
#pragma unroll
        for (int j = 0; j < 8; j++) {
            if (j <= jmax) {
                mA = fmaxf(mA, fmaxf(S[j][0], S[j][1]));
                mB = fmaxf(mB, fmaxf(S[j][2], S[j][3]));
            }
        }
        mA = qmax(mA); mB = qmax(mB);
        float mnA = fmaxf(mrow[0], mA), mnB = fmaxf(mrow[1], mB);
        float alA = __expf(mrow[0] - mnA), alB = __expf(mrow[1] - mnB);
        float sA = 0.0f, sB = 0.0f;
#pragma unroll
        for (int j = 0; j < 8; j++) {
            if (j <= jmax) {
                float p00 = __expf(S[j][0] - mnA);
                float p01 = __expf(S[j][1] - mnA);
                float p10 = __expf(S[j][2] - mnB);
                float p11 = __expf(S[j][3] - mnB);
                sA += p00 + p01; sB += p10 + p11;
                *(uint2*)&Ps[(16 * mg + grp) * APS + 8 * j + 2 * tig] =
                    make_uint2(to_tf32(p00), to_tf32(p01));
                *(uint2*)&Ps[(16 * mg + grp + 8) * APS + 8 * j + 2 * tig] =
                    make_uint2(to_tf32(p10), to_tf32(p11));
            }
        }
        sA = qsum(sA); sB = qsum(sB);
        lrow[0] = lrow[0] * alA + sA; mrow[0] = mnA;
        lrow[1] = lrow[1] * alB + sB; mrow[1] = mnB;
#pragma unroll
        for (int j = 0; j < 8; j++) {
            O[j][0] *= alA; O[j][1] *= alA;
            O[j][2] *= alB; O[j][3] *= alB;
        }
        __syncwarp();

        // ---- O += P @ V ----
#pragma unroll
        for (int ks = 0; ks < 8; ks++) {
            if (ks <= jmax) {
                uint32_t pa[4];
                pa[0] = Pu[(16 * mg + grp) * APS + 8 * ks + tig];
                pa[1] = Pu[(16 * mg + grp + 8) * APS + 8 * ks + tig];
                pa[2] = Pu[(16 * mg + grp) * APS + 8 * ks + tig + 4];
                pa[3] = Pu[(16 * mg + grp + 8) * APS + 8 * ks + tig + 4];
#pragma unroll
                for (int j = 0; j < 8; j++) {
                    uint32_t vb[2];
                    vb[0] = Vu[(8 * ks + tig) * AVS + 8 * j + grp];
                    vb[1] = Vu[(8 * ks + tig + 4) * AVS + 8 * j + grp];
                    mma_tf32(O[j], pa, vb);
                }
            }
        }

        // ---- stage next V ----
        if (hn) {
            float* Vn = Vs + (cur ^ 1) * VBUF;
#pragma unroll
            for (int i = 0; i < 8; i++)
                *(float4*)&Vn[(lr + 8 * i) * AVS + lc4 * 4] = vreg[i];
        }
        __syncthreads();
    }

    // write split partials
    const size_t row = (size_t)b * SEQ + 64 * t + 16 * mg + grp;
#pragma unroll
    for (int j = 0; j < 8; j++) {
        *(float2*)&g_osc[split][row * HDIM + 8 * j + 2 * tig] =
            make_float2(O[j][0], O[j][1]);
        *(float2*)&g_osc[split][(row + 8) * HDIM + 8 * j + 2 * tig] =
            make_float2(O[j][2], O[j][3]);
    }
    if (tig == 0) {
        g_ml[split][row * 2]           = mrow[0];
        g_ml[split][row * 2 + 1]       = lrow[0];
        g_ml[split][(row + 8) * 2]     = mrow[1];
        g_ml[split][(row + 8) * 2 + 1] = lrow[1];
    }
}

__global__ __launch_bounds__(128) void attn_tc(void)
{
    extern __shared__ float sm[];
    float* Qs = sm;
    float* Ks = Qs + 64 * AQS;
    float* Vs = Ks + 2 * KBUF;
    float* Ps = Vs + 2 * VBUF;

    const int pair = blockIdx.x;
    const int split = blockIdx.y;
    const int b = blockIdx.z;

    attn_tile_tc(b, pair, split, Qs, Ks, Vs, Ps);
    attn_tile_tc(b, 63 - pair, split, Qs, Ks, Vs, Ps);
}

// ---------------------------------------------------------------------------
// Merge split partials
// ---------------------------------------------------------------------------
__global__ __launch_bounds__(128) void merge_kernel(float* __restrict__ out)
{
    const size_t row = (size_t)blockIdx.x * 128 + threadIdx.x;
    float m0 = g_ml[0][row * 2], l0 = g_ml[0][row * 2 + 1];
    float m1 = g_ml[1][row * 2], l1 = g_ml[1][row * 2 + 1];
    float mm = fmaxf(m0, m1);
    float w0 = __expf(m0 - mm), w1 = __expf(m1 - mm);
    float inv = 1.0f / (w0 * l0 + w1 * l1);
    w0 *= inv; w1 *= inv;
#pragma unroll
    for (int c4 = 0; c4 < 16; c4++) {
        float4 a = *(const float4*)&g_osc[0][row * HDIM + c4 * 4];
        float4 c = *(const float4*)&g_osc[1][row * HDIM + c4 * 4];
        float4 o = make_float4(w0 * a.x + w1 * c.x, w0 * a.y + w1 * c.y,
                               w0 * a.z + w1 * c.z, w0 * a.w + w1 * c.w);
        *(float4*)&out[row * HDIM + c4 * 4] = o;
    }
}

// ---------------------------------------------------------------------------
extern "C" void kernel_launch(void* const* d_in, const int* in_sizes, int n_in,
                              void* d_out, int out_size)
{
    const float* x  = (const float*)d_in[0];
    const float* Wk = (const float*)d_in[1];
    const float* Wq = (const float*)d_in[2];
    const float* Wv = (const float*)d_in[3];
    float* out = (float*)d_out;

    cudaFuncSetAttribute(proj_tc, cudaFuncAttributeMaxDynamicSharedMemorySize, PROJ_SMEM);
    cudaFuncSetAttribute(attn_tc, cudaFuncAttributeMaxDynamicSharedMemorySize, ATTN_SMEM);

    dim3 pgrid(MROWS / 128, 3);
    proj_tc<<<pgrid, 256, PROJ_SMEM>>>(x, Wq, Wk, Wv);

    dim3 agrid(32, 2, BATCH);
    attn_tc<<<agrid, 128, ATTN_SMEM>>>();

    merge_kernel<<<MROWS / 128, 128>>>(out);
}

// round 10
// speedup vs baseline: 3.7964x; 1.3028x over previous
#include <cuda_runtime.h>
#include <cuda_bf16.h>
#include <math.h>
#include <cstdint>

#define BATCH 4
#define SEQ 4096
#define CDIM 1024
#define HDIM 64
#define MROWS (BATCH * SEQ)   // 16384

// Scratch (no cudaMalloc allowed). g_q/g_k/g_v hold tf32-rounded floats;
// g_q additionally pre-scaled by 1/sqrt(64). g_wt = [1024][192] tf32 weights
// (cols 0-63 = Wq, 64-127 = Wk, 128-191 = Wv).
__device__ float g_q[(size_t)MROWS * HDIM];
__device__ float g_k[(size_t)MROWS * HDIM];
__device__ float g_v[(size_t)MROWS * HDIM];
__device__ float g_wt[(size_t)CDIM * 192];
__device__ float g_osc[2][(size_t)MROWS * HDIM];   // split partial O
__device__ float g_ml[2][(size_t)MROWS * 2];       // split (m, l)

// ---------------------------------------------------------------------------
// helpers
// ---------------------------------------------------------------------------
__device__ __forceinline__ uint32_t to_tf32(float f) {
    uint32_t r;
    asm("cvt.rna.tf32.f32 %0, %1;" : "=r"(r) : "f"(f));
    return r;
}
__device__ __forceinline__ void mma_tf32(float* c, const uint32_t* a, const uint32_t* b) {
    asm volatile(
        "mma.sync.aligned.m16n8k8.row.col.f32.tf32.tf32.f32 "
        "{%0,%1,%2,%3}, {%4,%5,%6,%7}, {%8,%9}, {%0,%1,%2,%3};\n"
        : "+f"(c[0]), "+f"(c[1]), "+f"(c[2]), "+f"(c[3])
        : "r"(a[0]), "r"(a[1]), "r"(a[2]), "r"(a[3]), "r"(b[0]), "r"(b[1]));
}
__device__ __forceinline__ float qmax(float v) {
    v = fmaxf(v, __shfl_xor_sync(0xffffffffu, v, 1));
    v = fmaxf(v, __shfl_xor_sync(0xffffffffu, v, 2));
    return v;
}
__device__ __forceinline__ float qsum(float v) {
    v += __shfl_xor_sync(0xffffffffu, v, 1);
    v += __shfl_xor_sync(0xffffffffu, v, 2);
    return v;
}
__device__ __forceinline__ void cp16(uint32_t smem_dst, const void* gmem_src) {
    asm volatile("cp.async.cg.shared.global [%0], [%1], 16;"
                 :: "r"(smem_dst), "l"(gmem_src));
}
#define CP_COMMIT() asm volatile("cp.async.commit_group;" ::: "memory")
#define CP_WAIT0()  asm volatile("cp.async.wait_group 0;" ::: "memory")

// ---------------------------------------------------------------------------
// prep_w: convert all three weight matrices to tf32, packed [1024][192]
// ---------------------------------------------------------------------------
__global__ __launch_bounds__(256) void prep_w(
    const float* __restrict__ Wq,
    const float* __restrict__ Wk,
    const float* __restrict__ Wv)
{
    int idx = blockIdx.x * 256 + threadIdx.x;    // 0 .. 196607
    int k = idx / 192;
    int c = idx % 192;
    const float* W = (c < 64) ? Wq : (c < 128) ? Wk : Wv;
    g_wt[idx] = __uint_as_float(to_tf32(W[k * HDIM + (c & 63)]));
}

// ---------------------------------------------------------------------------
// Fused projection: {q,k,v} = x @ [Wq|Wk|Wv]  (x:[16384,1024], W:[1024,192])
// BM=64 (4 warps: 2 m-groups x 2 n-groups; warp tile 32x96), BK=32.
// cp.async double-buffered; A (x) raw fp32 in smem, cvt on fragments;
// B pre-converted tf32 (g_wt), raw loads.
// ---------------------------------------------------------------------------
#define FAS 36    // A stride: frag banks 4*grp+tig, conflict-free
#define FBS 200   // B stride: 200 mod 32 = 8 -> frag banks 8*tig+grp
#define FABUF (64 * FAS)          // 2304 floats
#define FBBUF (32 * FBS)          // 6400 floats
#define FBUF  (FABUF + FBBUF)     // 8704 floats
#define FPROJ_SMEM (2 * FBUF * 4) // 69632 bytes

__global__ __launch_bounds__(128) void proj_fused(const float* __restrict__ x)
{
    extern __shared__ float sm[];
    const uint32_t sbase = (uint32_t)__cvta_generic_to_shared(sm);

    const int tid = threadIdx.x;
    const int warp = tid >> 5;
    const int lane = tid & 31;
    const int grp = lane >> 2;
    const int tig = lane & 3;
    const int wm = warp >> 1;     // m-group: rows 32*wm .. 32*wm+31
    const int wn = warp & 1;      // n-group: cols 96*wn .. 96*wn+95
    const int row0 = blockIdx.x * 64;

    float acc[2][12][4];
#pragma unroll
    for (int m = 0; m < 2; m++)
#pragma unroll
        for (int j = 0; j < 12; j++)
#pragma unroll
            for (int e = 0; e < 4; e++) acc[m][j][e] = 0.0f;

    // ---- staging (cp.async), one group per k-chunk ----
    // A: 64 rows x 8 float4 = 512 chunks -> 4/thread
    // B: 32 rows x 48 float4 = 1536 chunks -> 12/thread
    auto issue_tile = [&](int it, int buf) {
        const int kc = it * 32;
        const uint32_t ab = sbase + (uint32_t)(buf * FBUF) * 4u;
        const uint32_t bb = ab + (uint32_t)FABUF * 4u;
#pragma unroll
        for (int i = 0; i < 4; i++) {
            int id = tid + i * 128;
            int r = id >> 3;
            int c4 = id & 7;
            cp16(ab + (uint32_t)(r * FAS + c4 * 4) * 4u,
                 &x[(size_t)(row0 + r) * CDIM + kc + c4 * 4]);
        }
#pragma unroll
        for (int i = 0; i < 12; i++) {
            int id = tid + i * 128;
            int r = id / 48;
            int c = id % 48;
            cp16(bb + (uint32_t)(r * FBS + c * 4) * 4u,
                 &g_wt[(size_t)(kc + r) * 192 + c * 4]);
        }
        CP_COMMIT();
    };

    issue_tile(0, 0);

    for (int it = 0; it < 32; it++) {
        const int cur = it & 1;
        CP_WAIT0();
        __syncthreads();
        if (it < 31) issue_tile(it + 1, cur ^ 1);

        const float* As = sm + cur * FBUF;
        const float* Bs = As + FABUF;

#pragma unroll
        for (int ks = 0; ks < 4; ks++) {
            uint32_t a[8];
#pragma unroll
            for (int m = 0; m < 2; m++) {
                const int rb = 32 * wm + 16 * m;
                a[4 * m + 0] = to_tf32(As[(rb + grp) * FAS + 8 * ks + tig]);
                a[4 * m + 1] = to_tf32(As[(rb + grp + 8) * FAS + 8 * ks + tig]);
                a[4 * m + 2] = to_tf32(As[(rb + grp) * FAS + 8 * ks + tig + 4]);
                a[4 * m + 3] = to_tf32(As[(rb + grp + 8) * FAS + 8 * ks + tig + 4]);
            }
#pragma unroll
            for (int jj = 0; jj < 12; jj++) {
                const int col = 96 * wn + 8 * jj;
                uint32_t b[2];
                b[0] = __float_as_uint(Bs[(8 * ks + tig) * FBS + col + grp]);
                b[1] = __float_as_uint(Bs[(8 * ks + tig + 4) * FBS + col + grp]);
                mma_tf32(acc[0][jj], a, b);
                mma_tf32(acc[1][jj], a + 4, b);
            }
        }
        __syncthreads();
    }

    // ---- epilogue: tf32-round (pre-scale q by 0.125) ----
#pragma unroll
    for (int m = 0; m < 2; m++) {
        const int row = row0 + 32 * wm + 16 * m + grp;
#pragma unroll
        for (int jj = 0; jj < 12; jj++) {
            const int gc = 96 * wn + 8 * jj;
            const int mat = gc >> 6;
            const int col = (gc & 63) + 2 * tig;
            float* out = (mat == 0) ? g_q : (mat == 1) ? g_k : g_v;
            const float scale = (mat == 0) ? 0.125f : 1.0f;
            float2 lo = make_float2(
                __uint_as_float(to_tf32(scale * acc[m][jj][0])),
                __uint_as_float(to_tf32(scale * acc[m][jj][1])));
            float2 hi = make_float2(
                __uint_as_float(to_tf32(scale * acc[m][jj][2])),
                __uint_as_float(to_tf32(scale * acc[m][jj][3])));
            *(float2*)&out[(size_t)row * HDIM + col] = lo;
            *(float2*)&out[(size_t)(row + 8) * HDIM + col] = hi;
        }
    }
}

// ---------------------------------------------------------------------------
// Attention via tf32 mma, cp.async double-buffered K/V.
// 64-row Q tiles, 4 warps x 16 rows; warp-local online softmax.
// Split-K parity + tile pairing (t, 63-t) -> 256 equal CTAs.
// ---------------------------------------------------------------------------
#define AQS 68   // Q/K stride
#define AVS 72   // V stride
#define APS 68   // P stride
#define KBUF (64 * AQS)
#define VBUF (64 * AVS)
#define ATTN_SMEM ((64 * AQS + 2 * KBUF + 2 * VBUF + 64 * APS) * 4)

__device__ __forceinline__ void attn_tile_tc(
    int b, int t, int split,
    float* Qs, float* Ks, float* Vs, float* Ps,
    uint32_t qb32, uint32_t kb32, uint32_t vb32)
{
    const int tid = threadIdx.x;
    const int mg = tid >> 5;
    const int lane = tid & 31;
    const int grp = lane >> 2;
    const int tig = lane & 3;
    const int lr = tid >> 4;      // base row 0..7 (step 8)
    const int lc4 = tid & 15;     // float4 col 0..15

    const float* kbase = g_k + (size_t)b * SEQ * HDIM;
    const float* vbase = g_v + (size_t)b * SEQ * HDIM;
    const float* qb = g_q + ((size_t)b * SEQ + 64 * t) * HDIM;

    __syncthreads();   // previous phase done with all smem

    // ---- prologue group: Q + first K/V into buffer 0 ----
#pragma unroll
    for (int i = 0; i < 8; i++)
        cp16(qb32 + (uint32_t)((lr + 8 * i) * AQS + lc4 * 4) * 4u,
             &qb[(size_t)(lr + 8 * i) * HDIM + lc4 * 4]);
    if (split <= t) {
        const float* kp = kbase + (size_t)(64 * split) * HDIM;
        const float* vp = vbase + (size_t)(64 * split) * HDIM;
#pragma unroll
        for (int i = 0; i < 8; i++) {
            cp16(kb32 + (uint32_t)((lr + 8 * i) * AQS + lc4 * 4) * 4u,
                 &kp[(size_t)(lr + 8 * i) * HDIM + lc4 * 4]);
            cp16(vb32 + (uint32_t)((lr + 8 * i) * AVS + lc4 * 4) * 4u,
                 &vp[(size_t)(lr + 8 * i) * HDIM + lc4 * 4]);
        }
    }
    CP_COMMIT();

    float O[8][4];
#pragma unroll
    for (int j = 0; j < 8; j++)
#pragma unroll
        for (int e = 0; e < 4; e++) O[j][e] = 0.0f;
    float mrow[2] = {-1e30f, -1e30f};
    float lrow[2] = {0.0f, 0.0f};

    const uint32_t* Qu = (const uint32_t*)Qs;
    const uint32_t* Pu = (const uint32_t*)Ps;

    int idx = 0;
    for (int kb = split; kb <= t; kb += 2, idx++) {
        const int cur = idx & 1;
        const bool hn = (kb + 2 <= t);

        CP_WAIT0();
        __syncthreads();

        // issue next K/V into the other buffer (its readers drained above)
        if (hn) {
            const float* kp = kbase + (size_t)(64 * (kb + 2)) * HDIM;
            const float* vp = vbase + (size_t)(64 * (kb + 2)) * HDIM;
            const uint32_t kn = kb32 + (uint32_t)((cur ^ 1) * KBUF) * 4u;
            const uint32_t vn = vb32 + (uint32_t)((cur ^ 1) * VBUF) * 4u;
#pragma unroll
            for (int i = 0; i < 8; i++) {
                cp16(kn + (uint32_t)((lr + 8 * i) * AQS + lc4 * 4) * 4u,
                     &kp[(size_t)(lr + 8 * i) * HDIM + lc4 * 4]);
                cp16(vn + (uint32_t)((lr + 8 * i) * AVS + lc4 * 4) * 4u,
                     &vp[(size_t)(lr + 8 * i) * HDIM + lc4 * 4]);
            }
            CP_COMMIT();
        }

        const uint32_t* Ku = (const uint32_t*)(Ks + cur * KBUF);
        const uint32_t* Vu = (const uint32_t*)(Vs + cur * VBUF);

        const bool diag = (kb == t);
        const int jmax = diag ? (2 * mg + 1) : 7;

        // ---- S = Q K^T ----
        float S[8][4];
#pragma unroll
        for (int j = 0; j < 8; j++)
#pragma unroll
            for (int e = 0; e < 4; e++) S[j][e] = 0.0f;
#pragma unroll
        for (int ks = 0; ks < 8; ks++) {
            uint32_t a[4];
            a[0] = Qu[(16 * mg + grp) * AQS + 8 * ks + tig];
            a[1] = Qu[(16 * mg + grp + 8) * AQS + 8 * ks + tig];
            a[2] = Qu[(16 * mg + grp) * AQS + 8 * ks + tig + 4];
            a[3] = Qu[(16 * mg + grp + 8) * AQS + 8 * ks + tig + 4];
#pragma unroll
            for (int j = 0; j < 8; j++) {
                if (j <= jmax) {
                    uint32_t bf[2];
                    bf[0] = Ku[(8 * j + grp) * AQS + 8 * ks + tig];
                    bf[1] = Ku[(8 * j + grp) * AQS + 8 * ks + tig + 4];
                    mma_tf32(S[j], a, bf);
                }
            }
        }

        // ---- mask diagonal ----
        if (diag) {
#pragma unroll
            for (int j = 0; j < 8; j++) {
                if (j <= jmax) {
#pragma unroll
                    for (int e = 0; e < 2; e++) {
                        int key = 8 * j + 2 * tig + e;
                        if (key > 16 * mg + grp)     S[j][e]     = -1e30f;
                        if (key > 16 * mg + grp + 8) S[j][2 + e] = -1e30f;
                    }
                }
            }
        }

        // ---- online softmax ----
        float mA = -1e30f, mB = -1e30f;
#pragma unroll
        for (int j = 0; j < 8; j++) {
            if (j <= jmax) {
                mA = fmaxf(mA, fmaxf(S[j][0], S[j][1]));
                mB = fmaxf(mB, fmaxf(S[j][2], S[j][3]));
            }
        }
        mA = qmax(mA); mB = qmax(mB);
        float mnA = fmaxf(mrow[0], mA), mnB = fmaxf(mrow[1], mB);
        float alA = __expf(mrow[0] - mnA), alB = __expf(mrow[1] - mnB);
        float sA = 0.0f, sB = 0.0f;
#pragma unroll
        for (int j = 0; j < 8; j++) {
            if (j <= jmax) {
                float p00 = __expf(S[j][0] - mnA);
                float p01 = __expf(S[j][1] - mnA);
                float p10 = __expf(S[j][2] - mnB);
                float p11 = __expf(S[j][3] - mnB);
                sA += p00 + p01; sB += p10 + p11;
                *(uint2*)&Ps[(16 * mg + grp) * APS + 8 * j + 2 * tig] =
                    make_uint2(to_tf32(p00), to_tf32(p01));
                *(uint2*)&Ps[(16 * mg + grp + 8) * APS + 8 * j + 2 * tig] =
                    make_uint2(to_tf32(p10), to_tf32(p11));
            }
        }
        sA = qsum(sA); sB = qsum(sB);
        lrow[0] = lrow[0] * alA + sA; mrow[0] = mnA;
        lrow[1] = lrow[1] * alB + sB; mrow[1] = mnB;
#pragma unroll
        for (int j = 0; j < 8; j++) {
            O[j][0] *= alA; O[j][1] *= alA;
            O[j][2] *= alB; O[j][3] *= alB;
        }
        __syncwarp();   // Ps produced/consumed within this warp only

        // ---- O += P @ V ----
#pragma unroll
        for (int ks = 0; ks < 8; ks++) {
            if (ks <= jmax) {
                uint32_t pa[4];
                pa[0] = Pu[(16 * mg + grp) * APS + 8 * ks + tig];
                pa[1] = Pu[(16 * mg + grp + 8) * APS + 8 * ks + tig];
                pa[2] = Pu[(16 * mg + grp) * APS + 8 * ks + tig + 4];
                pa[3] = Pu[(16 * mg + grp + 8) * APS + 8 * ks + tig + 4];
#pragma unroll
                for (int j = 0; j < 8; j++) {
                    uint32_t vb[2];
                    vb[0] = Vu[(8 * ks + tig) * AVS + 8 * j + grp];
                    vb[1] = Vu[(8 * ks + tig + 4) * AVS + 8 * j + grp];
                    mma_tf32(O[j], pa, vb);
                }
            }
        }
    }

    // write split partials
    const size_t row = (size_t)b * SEQ + 64 * t + 16 * mg + grp;
#pragma unroll
    for (int j = 0; j < 8; j++) {
        *(float2*)&g_osc[split][row * HDIM + 8 * j + 2 * tig] =
            make_float2(O[j][0], O[j][1]);
        *(float2*)&g_osc[split][(row + 8) * HDIM + 8 * j + 2 * tig] =
            make_float2(O[j][2], O[j][3]);
    }
    if (tig == 0) {
        g_ml[split][row * 2]           = mrow[0];
        g_ml[split][row * 2 + 1]       = lrow[0];
        g_ml[split][(row + 8) * 2]     = mrow[1];
        g_ml[split][(row + 8) * 2 + 1] = lrow[1];
    }
}

__global__ __launch_bounds__(128) void attn_tc(void)
{
    extern __shared__ float sm[];
    float* Qs = sm;
    float* Ks = Qs + 64 * AQS;
    float* Vs = Ks + 2 * KBUF;
    float* Ps = Vs + 2 * VBUF;

    const uint32_t sbase = (uint32_t)__cvta_generic_to_shared(sm);
    const uint32_t qb32 = sbase;
    const uint32_t kb32 = sbase + (uint32_t)(64 * AQS) * 4u;
    const uint32_t vb32 = kb32 + (uint32_t)(2 * KBUF) * 4u;

    const int pair = blockIdx.x;
    const int split = blockIdx.y;
    const int b = blockIdx.z;

    attn_tile_tc(b, pair, split, Qs, Ks, Vs, Ps, qb32, kb32, vb32);
    attn_tile_tc(b, 63 - pair, split, Qs, Ks, Vs, Ps, qb32, kb32, vb32);
}

// ---------------------------------------------------------------------------
// Merge split partials
// ---------------------------------------------------------------------------
__global__ __launch_bounds__(128) void merge_kernel(float* __restrict__ out)
{
    const size_t row = (size_t)blockIdx.x * 128 + threadIdx.x;
    float m0 = g_ml[0][row * 2], l0 = g_ml[0][row * 2 + 1];
    float m1 = g_ml[1][row * 2], l1 = g_ml[1][row * 2 + 1];
    float mm = fmaxf(m0, m1);
    float w0 = __expf(m0 - mm), w1 = __expf(m1 - mm);
    float inv = 1.0f / (w0 * l0 + w1 * l1);
    w0 *= inv; w1 *= inv;
#pragma unroll
    for (int c4 = 0; c4 < 16; c4++) {
        float4 a = *(const float4*)&g_osc[0][row * HDIM + c4 * 4];
        float4 c = *(const float4*)&g_osc[1][row * HDIM + c4 * 4];
        float4 o = make_float4(w0 * a.x + w1 * c.x, w0 * a.y + w1 * c.y,
                               w0 * a.z + w1 * c.z, w0 * a.w + w1 * c.w);
        *(float4*)&out[row * HDIM + c4 * 4] = o;
    }
}

// ---------------------------------------------------------------------------
extern "C" void kernel_launch(void* const* d_in, const int* in_sizes, int n_in,
                              void* d_out, int out_size)
{
    const float* x  = (const float*)d_in[0];
    const float* Wk = (const float*)d_in[1];
    const float* Wq = (const float*)d_in[2];
    const float* Wv = (const float*)d_in[3];
    float* out = (float*)d_out;

    cudaFuncSetAttribute(proj_fused, cudaFuncAttributeMaxDynamicSharedMemorySize, FPROJ_SMEM);
    cudaFuncSetAttribute(attn_tc, cudaFuncAttributeMaxDynamicSharedMemorySize, ATTN_SMEM);

    prep_w<<<(CDIM * 192) / 256, 256>>>(Wq, Wk, Wv);
    proj_fused<<<MROWS / 64, 128, FPROJ_SMEM>>>(x);

    dim3 agrid(32, 2, BATCH);
    attn_tc<<<agrid, 128, ATTN_SMEM>>>();

    merge_kernel<<<MROWS / 128, 128>>>(out);
}